// round 8
// baseline (speedup 1.0000x reference)
#include <cuda_runtime.h>

#define BATCH 8
#define NPTS  2048
#define KNN   20
// 1/sqrt(1 + 1e-5)
#define BN_INV 0.99999500003749971f
#define NEG_INF -3.4e38f

typedef unsigned long long ull;

// ---------------- packed f32x2 helpers (sm_103a FFMA2 path) -------------------
__device__ __forceinline__ ull pack2(float v) {
    ull r;
    asm("mov.b64 %0, {%1, %1};" : "=l"(r) : "r"(__float_as_uint(v)));
    return r;
}
__device__ __forceinline__ ull pack2f(float a, float b) {
    ull r;
    asm("mov.b64 %0, {%1, %2};" : "=l"(r) : "r"(__float_as_uint(a)), "r"(__float_as_uint(b)));
    return r;
}
__device__ __forceinline__ void unpack2(ull p, float& lo, float& hi) {
    unsigned int a, b;
    asm("mov.b64 {%0, %1}, %2;" : "=r"(a), "=r"(b) : "l"(p));
    lo = __uint_as_float(a); hi = __uint_as_float(b);
}
__device__ __forceinline__ ull ffma2(ull a, ull b, ull c) {
    ull d;
    asm("fma.rn.f32x2 %0, %1, %2, %3;" : "=l"(d) : "l"(a), "l"(b), "l"(c));
    return d;
}

// ---------------- scratch (static device memory; no allocs allowed) ----------
__device__ float g_xsq[BATCH][NPTS];
__device__ float g_dist[BATCH][NPTS][NPTS];      // 134 MB scratch for kNN scores
__device__ int   g_idx[BATCH][NPTS][KNN];
__device__ float g_yt[BATCH][NPTS][512];         // [m][0..Co) = y = Wa*x, [Co..2Co) = t = (Wb-Wa)*x
__device__ float g_xc[BATCH][512][NPTS];         // concat of x1..x4 (channel offsets 0,64,128,256)
__device__ int   g_pool[BATCH][1024];            // float bits, atomicMax over non-negative floats
__device__ float g_fc1[BATCH][512];
__device__ float g_fc2[BATCH][256];

// ---------------- per-point squared norm --------------------------------------
__global__ void xsq_kernel(const float* __restrict__ x, int xbs, int C) {
    int b = blockIdx.y;
    int m = blockIdx.x * blockDim.x + threadIdx.x;
    float s = 0.f;
    for (int c = 0; c < C; ++c) {
        float v = x[b * xbs + c * NPTS + m];
        s = fmaf(v, v, s);
    }
    g_xsq[b][m] = s;
}

// ---------------- kNN score matrix: score[n][m] = 2*<x_n,x_m> - xsq[m] --------
// Tiles 64(n) x 128(m), per-thread 4x8 via packed f32x2 FMA. Blocks fully below
// the diagonal are skipped; kept blocks also write the transposed tile
// (score[m][n] = 2*dot - xsq[n]) via shared staging. Overlapping writes from
// straddling blocks produce bit-identical values (same summation order).
__global__ void dist_kernel(const float* __restrict__ x, int xbs, int C) {
    int bx = blockIdx.x, by = blockIdx.y;
    if (2 * by + 2 <= bx) return;   // whole block strictly below diagonal
    __shared__ __align__(16) float As[16][64];
    __shared__ __align__(16) float Bs[16][128];
    __shared__ float sT[128][65];
    int b  = blockIdx.z;
    int n0 = bx * 64;
    int m0 = by * 128;
    int tid = threadIdx.x;
    int rn = (tid >> 4) << 2;   // n offset within tile (0..60)
    int cm = (tid & 15) << 3;   // m offset within tile (0..120), 8-wide
    ull acc[4][4];
#pragma unroll
    for (int i = 0; i < 4; i++)
#pragma unroll
        for (int jp = 0; jp < 4; jp++) acc[i][jp] = 0ull;

    for (int k0 = 0; k0 < C; k0 += 16) {
#pragma unroll 4
        for (int t = tid; t < 1024; t += 256) {
            int kk = t >> 6, nn = t & 63;
            int c = k0 + kk;
            As[kk][nn] = (c < C) ? x[b * xbs + c * NPTS + n0 + nn] : 0.f;
        }
#pragma unroll 8
        for (int t = tid; t < 2048; t += 256) {
            int kk = t >> 7, mm = t & 127;
            int c = k0 + kk;
            Bs[kk][mm] = (c < C) ? x[b * xbs + c * NPTS + m0 + mm] : 0.f;
        }
        __syncthreads();
#pragma unroll
        for (int kk = 0; kk < 16; kk++) {
            ull a2[4], b2[4];
#pragma unroll
            for (int i = 0; i < 4; i++) a2[i] = pack2(As[kk][rn + i]);
#pragma unroll
            for (int jp = 0; jp < 4; jp++)
                b2[jp] = *reinterpret_cast<const ull*>(&Bs[kk][cm + 2 * jp]);
#pragma unroll
            for (int i = 0; i < 4; i++)
#pragma unroll
                for (int jp = 0; jp < 4; jp++)
                    acc[i][jp] = ffma2(a2[i], b2[jp], acc[i][jp]);
        }
        __syncthreads();
    }
    // direct write: score[n][m] = 2*dot - xsq[m]
    ull two2 = pack2(2.0f);
    ull nx[4];
#pragma unroll
    for (int jp = 0; jp < 4; jp++)
        nx[jp] = pack2f(-g_xsq[b][m0 + cm + 2 * jp], -g_xsq[b][m0 + cm + 2 * jp + 1]);
#pragma unroll
    for (int i = 0; i < 4; i++) {
        float4 v0, v1;
        ull p;
        p = ffma2(acc[i][0], two2, nx[0]); unpack2(p, v0.x, v0.y);
        p = ffma2(acc[i][1], two2, nx[1]); unpack2(p, v0.z, v0.w);
        p = ffma2(acc[i][2], two2, nx[2]); unpack2(p, v1.x, v1.y);
        p = ffma2(acc[i][3], two2, nx[3]); unpack2(p, v1.z, v1.w);
        float4* dst = reinterpret_cast<float4*>(&g_dist[b][n0 + rn + i][m0 + cm]);
        dst[0] = v0; dst[1] = v1;
    }
    // transposed write: score[m][n] = 2*dot - xsq[n] (raw dots staged in sT)
#pragma unroll
    for (int i = 0; i < 4; i++)
#pragma unroll
        for (int jp = 0; jp < 4; jp++) {
            float lo, hi; unpack2(acc[i][jp], lo, hi);
            sT[cm + 2 * jp][rn + i]     = lo;
            sT[cm + 2 * jp + 1][rn + i] = hi;
        }
    __syncthreads();
#pragma unroll 8
    for (int t = tid; t < 8192; t += 256) {
        int mm = t >> 6, nn = t & 63;
        g_dist[b][m0 + mm][n0 + nn] = fmaf(2.f, sT[mm][nn], -g_xsq[b][n0 + nn]);
    }
}

// ---------------- top-k per row: warp-per-row register argmax extraction ------
__global__ void topk_kernel() {
    int b    = blockIdx.y;
    int warp = threadIdx.x >> 5;
    int lane = threadIdx.x & 31;
    int n    = blockIdx.x * 8 + warp;

    const float4* row = reinterpret_cast<const float4*>(&g_dist[b][n][0]);
    float val[64];
    float chmax[4];
    int   chidx[4];

#pragma unroll
    for (int q = 0; q < 16; q++) {
        float4 v = row[lane + 32 * q];
        val[q * 4 + 0] = v.x;
        val[q * 4 + 1] = v.y;
        val[q * 4 + 2] = v.z;
        val[q * 4 + 3] = v.w;
    }
    // global element index of val[j]: 4*lane + 128*(j>>2) + (j&3)
#pragma unroll
    for (int c = 0; c < 4; c++) {
        float nm = NEG_INF; int ni = 0;
#pragma unroll
        for (int i = 0; i < 16; i++) {
            int j = c * 16 + i;
            int g = 4 * lane + 128 * (j >> 2) + (j & 3);
            if (val[j] > nm) { nm = val[j]; ni = g; }
        }
        chmax[c] = nm; chidx[c] = ni;
    }

    for (int kk = 0; kk < KNN; kk++) {
        float lm = chmax[0]; int li = chidx[0];
#pragma unroll
        for (int c = 1; c < 4; c++)
            if (chmax[c] > lm) { lm = chmax[c]; li = chidx[c]; }
#pragma unroll
        for (int s = 16; s; s >>= 1) {
            float ov = __shfl_down_sync(0xffffffffu, lm, s);
            int   oi = __shfl_down_sync(0xffffffffu, li, s);
            if (ov > lm) { lm = ov; li = oi; }
        }
        lm = __shfl_sync(0xffffffffu, lm, 0);
        li = __shfl_sync(0xffffffffu, li, 0);
        if (lane == 0) g_idx[b][n][kk] = li;
        if (((li >> 2) & 31) == lane) {
            bool done = false;
#pragma unroll
            for (int c = 0; c < 4; c++) {
                if (!done && chmax[c] == lm) {
                    done = true;
                    float nm = NEG_INF; int ni = 0;
#pragma unroll
                    for (int i = 0; i < 16; i++) {
                        int j = c * 16 + i;
                        if (val[j] == lm) val[j] = NEG_INF;
                        int g = 4 * lane + 128 * (j >> 2) + (j & 3);
                        if (val[j] > nm) { nm = val[j]; ni = g; }
                    }
                    chmax[c] = nm; chidx[c] = ni;
                }
            }
        }
    }
}

// ---------------- y/t GEMM: out[b][m][o] for o in [0,2Co): y then t ----------
// Tiles 64(o) x 128(m), per-thread 4x8 packed f32x2.
__global__ void yt_kernel(const float* __restrict__ x, int xbs, int C,
                          const float* __restrict__ w, int Co) {
    __shared__ __align__(16) float Ws[16][64];
    __shared__ __align__(16) float Xs[16][128];
    int b  = blockIdx.z;
    int o0 = blockIdx.x * 64;
    int m0 = blockIdx.y * 128;
    int tid = threadIdx.x;
    int ro = (tid >> 4) << 2;
    int cm = (tid & 15) << 3;
    int twoC = 2 * C;
    ull acc[4][4];
#pragma unroll
    for (int i = 0; i < 4; i++)
#pragma unroll
        for (int jp = 0; jp < 4; jp++) acc[i][jp] = 0ull;

    for (int k0 = 0; k0 < C; k0 += 16) {
        for (int t = tid; t < 1024; t += 256) {
            int kk = t & 15, oo = t >> 4;
            int c = k0 + kk;
            float wv = 0.f;
            if (c < C) {
                int o = o0 + oo;
                if (o < Co) wv = w[o * twoC + c];
                else {
                    int o2 = o - Co;
                    wv = w[o2 * twoC + C + c] - w[o2 * twoC + c];
                }
            }
            Ws[kk][oo] = wv;
        }
        for (int t = tid; t < 2048; t += 256) {
            int kk = t >> 7, mm = t & 127;
            int c = k0 + kk;
            Xs[kk][mm] = (c < C) ? x[b * xbs + c * NPTS + m0 + mm] : 0.f;
        }
        __syncthreads();
#pragma unroll
        for (int kk = 0; kk < 16; kk++) {
            ull a2[4], b2[4];
#pragma unroll
            for (int i = 0; i < 4; i++) a2[i] = pack2(Ws[kk][ro + i]);
#pragma unroll
            for (int jp = 0; jp < 4; jp++)
                b2[jp] = *reinterpret_cast<const ull*>(&Xs[kk][cm + 2 * jp]);
#pragma unroll
            for (int i = 0; i < 4; i++)
#pragma unroll
                for (int jp = 0; jp < 4; jp++)
                    acc[i][jp] = ffma2(a2[i], b2[jp], acc[i][jp]);
        }
        __syncthreads();
    }
#pragma unroll
    for (int jp = 0; jp < 4; jp++) {
        float lo0, hi0, lo1, hi1, lo2, hi2, lo3, hi3;
        unpack2(acc[0][jp], lo0, hi0);
        unpack2(acc[1][jp], lo1, hi1);
        unpack2(acc[2][jp], lo2, hi2);
        unpack2(acc[3][jp], lo3, hi3);
        float4 vlo = make_float4(lo0, lo1, lo2, lo3);
        float4 vhi = make_float4(hi0, hi1, hi2, hi3);
        *reinterpret_cast<float4*>(&g_yt[b][m0 + cm + 2 * jp][o0 + ro])     = vlo;
        *reinterpret_cast<float4*>(&g_yt[b][m0 + cm + 2 * jp + 1][o0 + ro]) = vhi;
    }
}

// ---------------- gather + max_k + bn/relu, transposed write into concat buf --
__global__ void gathermax_kernel(int Co, const float* __restrict__ bg,
                                 const float* __restrict__ bb, int chanoff) {
    __shared__ int   sidx[32][KNN];
    __shared__ float sval[32][257];   // padded: stride 257 -> conflict-free transpose
    int b  = blockIdx.y;
    int n0 = blockIdx.x * 32;
    int tid = threadIdx.x;
    for (int t = tid; t < 32 * KNN; t += 256)
        sidx[t / KNN][t % KNN] = g_idx[b][n0 + t / KNN][t % KNN];
    __syncthreads();
    for (int t = tid; t < 32 * Co; t += 256) {
        int nn = t / Co, o = t - nn * Co;
        float mv = NEG_INF;
#pragma unroll
        for (int kk = 0; kk < KNN; kk++)
            mv = fmaxf(mv, g_yt[b][sidx[nn][kk]][o]);
        float tv = g_yt[b][n0 + nn][Co + o];
        float s  = bg[o] * BN_INV;
        sval[nn][o] = fmaxf(fmaf(s, mv + tv, bb[o]), 0.f);
    }
    __syncthreads();
    for (int t = tid; t < 32 * Co; t += 256) {
        int o = t >> 5, nn = t & 31;
        g_xc[b][chanoff + o][n0 + nn] = sval[nn][o];
    }
}

// ---------------- conv5 (1024x512 GEMM) + bn/relu + global max over n ---------
__global__ void init_pool_kernel() { g_pool[blockIdx.x][threadIdx.x] = 0; }

__global__ void conv5_kernel(const float* __restrict__ w5,
                             const float* __restrict__ g5,
                             const float* __restrict__ b5) {
    __shared__ __align__(16) float Ws[16][64];
    __shared__ __align__(16) float Xs[16][128];
    __shared__ float sred[64][17];
    int b  = blockIdx.z;
    int o0 = blockIdx.x * 64;
    int n0 = blockIdx.y * 128;
    int tid = threadIdx.x;
    int ro = (tid >> 4) << 2;
    int cn = (tid & 15) << 3;
    ull acc[4][4];
#pragma unroll
    for (int i = 0; i < 4; i++)
#pragma unroll
        for (int jp = 0; jp < 4; jp++) acc[i][jp] = 0ull;

    for (int k0 = 0; k0 < 512; k0 += 16) {
        for (int t = tid; t < 1024; t += 256) {
            int kk = t & 15, oo = t >> 4;
            Ws[kk][oo] = w5[(o0 + oo) * 512 + k0 + kk];
        }
        for (int t = tid; t < 2048; t += 256) {
            int kk = t >> 7, nn = t & 127;
            Xs[kk][nn] = g_xc[b][k0 + kk][n0 + nn];
        }
        __syncthreads();
#pragma unroll
        for (int kk = 0; kk < 16; kk++) {
            ull a2[4], b2[4];
#pragma unroll
            for (int i = 0; i < 4; i++) a2[i] = pack2(Ws[kk][ro + i]);
#pragma unroll
            for (int jp = 0; jp < 4; jp++)
                b2[jp] = *reinterpret_cast<const ull*>(&Xs[kk][cn + 2 * jp]);
#pragma unroll
            for (int i = 0; i < 4; i++)
#pragma unroll
                for (int jp = 0; jp < 4; jp++)
                    acc[i][jp] = ffma2(a2[i], b2[jp], acc[i][jp]);
        }
        __syncthreads();
    }
#pragma unroll
    for (int i = 0; i < 4; i++) {
        float s = g5[o0 + ro + i] * BN_INV;
        float bias = b5[o0 + ro + i];
        float m = 0.f;
#pragma unroll
        for (int jp = 0; jp < 4; jp++) {
            float lo, hi; unpack2(acc[i][jp], lo, hi);
            m = fmaxf(m, fmaxf(fmaf(s, lo, bias), 0.f));
            m = fmaxf(m, fmaxf(fmaf(s, hi, bias), 0.f));
        }
        sred[ro + i][tid & 15] = m;
    }
    __syncthreads();
    if (tid < 64) {
        float m = sred[tid][0];
#pragma unroll
        for (int c = 1; c < 16; c++) m = fmaxf(m, sred[tid][c]);
        atomicMax(&g_pool[b][o0 + tid], __float_as_int(m));  // m >= 0: int bits ordered
    }
}

// ---------------- FC head -----------------------------------------------------
__device__ __forceinline__ float warp_sum(float v) {
#pragma unroll
    for (int s = 16; s > 0; s >>= 1) v += __shfl_down_sync(0xffffffffu, v, s);
    return v;
}

__global__ void fc1_kernel(const float* __restrict__ w, const float* __restrict__ bg,
                           const float* __restrict__ bb) {
    int gw   = (blockIdx.x * blockDim.x + threadIdx.x) >> 5;
    int lane = threadIdx.x & 31;
    if (gw >= BATCH * 512) return;
    int b = gw >> 9, j = gw & 511;
    const float* in = reinterpret_cast<const float*>(&g_pool[b][0]);
    float acc = 0.f;
    for (int i = lane; i < 1024; i += 32) acc = fmaf(in[i], w[j * 1024 + i], acc);
    acc = warp_sum(acc);
    if (lane == 0) g_fc1[b][j] = fmaxf(fmaf(bg[j] * BN_INV, acc, bb[j]), 0.f);
}

__global__ void fc2_kernel(const float* __restrict__ w, const float* __restrict__ bg,
                           const float* __restrict__ bb) {
    int gw   = (blockIdx.x * blockDim.x + threadIdx.x) >> 5;
    int lane = threadIdx.x & 31;
    if (gw >= BATCH * 256) return;
    int b = gw >> 8, j = gw & 255;
    float acc = 0.f;
    for (int i = lane; i < 512; i += 32) acc = fmaf(g_fc1[b][i], w[j * 512 + i], acc);
    acc = warp_sum(acc);
    if (lane == 0) g_fc2[b][j] = fmaxf(fmaf(bg[j] * BN_INV, acc, bb[j]), 0.f);
}

__global__ void fc3_kernel(const float* __restrict__ w, float* __restrict__ out) {
    int gw   = (blockIdx.x * blockDim.x + threadIdx.x) >> 5;
    int lane = threadIdx.x & 31;
    if (gw >= BATCH * 40) return;
    int b = gw / 40, j = gw % 40;
    float acc = 0.f;
    for (int i = lane; i < 256; i += 32) acc = fmaf(g_fc2[b][i], w[j * 256 + i], acc);
    acc = warp_sum(acc);
    if (lane == 0) out[b * 40 + j] = acc;
}

// ---------------- host driver --------------------------------------------------
static void run_layer(const float* x, int xbs, int C, const float* w, int Co,
                      const float* bg, const float* bb, int chanoff) {
    xsq_kernel<<<dim3(NPTS / 256, BATCH), 256>>>(x, xbs, C);
    dist_kernel<<<dim3(32, 16, BATCH), 256>>>(x, xbs, C);
    topk_kernel<<<dim3(NPTS / 8, BATCH), 256>>>();
    yt_kernel<<<dim3(2 * Co / 64, NPTS / 128, BATCH), 256>>>(x, xbs, C, w, Co);
    gathermax_kernel<<<dim3(NPTS / 32, BATCH), 256>>>(Co, bg, bb, chanoff);
}

extern "C" void kernel_launch(void* const* d_in, const int* in_sizes, int n_in,
                              void* d_out, int out_size) {
    const float* x   = (const float*)d_in[0];
    const float* w1  = (const float*)d_in[1];
    const float* w2  = (const float*)d_in[2];
    const float* w3  = (const float*)d_in[3];
    const float* w4  = (const float*)d_in[4];
    const float* w5  = (const float*)d_in[5];
    const float* fw1 = (const float*)d_in[6];
    const float* fw2 = (const float*)d_in[7];
    const float* fw3 = (const float*)d_in[8];
    const float* g1 = (const float*)d_in[9],  *b1 = (const float*)d_in[10];
    const float* g2 = (const float*)d_in[11], *b2 = (const float*)d_in[12];
    const float* g3 = (const float*)d_in[13], *b3 = (const float*)d_in[14];
    const float* g4 = (const float*)d_in[15], *b4 = (const float*)d_in[16];
    const float* g5 = (const float*)d_in[17], *b5 = (const float*)d_in[18];
    const float* g6 = (const float*)d_in[19], *b6 = (const float*)d_in[20];
    const float* g7 = (const float*)d_in[21], *b7 = (const float*)d_in[22];

    float* xc = nullptr;
    cudaGetSymbolAddress((void**)&xc, g_xc);

    init_pool_kernel<<<BATCH, 1024>>>();

    run_layer(x,                3 * NPTS,   3,   w1, 64,  g1, b1, 0);
    run_layer(xc,               512 * NPTS, 64,  w2, 64,  g2, b2, 64);
    run_layer(xc + 64 * NPTS,   512 * NPTS, 64,  w3, 128, g3, b3, 128);
    run_layer(xc + 128 * NPTS,  512 * NPTS, 128, w4, 256, g4, b4, 256);

    conv5_kernel<<<dim3(16, 16, BATCH), 256>>>(w5, g5, b5);

    fc1_kernel<<<512, 256>>>(fw1, g6, b6);
    fc2_kernel<<<256, 256>>>(fw2, g7, b7);
    fc3_kernel<<<40, 256>>>(fw3, (float*)d_out);
}

// round 15
// speedup vs baseline: 1.0262x; 1.0262x over previous
#include <cuda_runtime.h>

#define BATCH 8
#define NPTS  2048
#define KNN   20
// 1/sqrt(1 + 1e-5)
#define BN_INV 0.99999500003749971f
#define NEG_INF -3.4e38f

// ---------------- scratch (static device memory; no allocs allowed) ----------
__device__ float g_xsq[BATCH][NPTS];
__device__ float g_dist[BATCH][NPTS][NPTS];      // 134 MB scratch for kNN scores
__device__ int   g_idx[BATCH][NPTS][KNN];
__device__ float g_yt[BATCH][NPTS][512];         // [m][0..Co) = y = Wa*x, [Co..2Co) = t = (Wb-Wa)*x
__device__ float g_xc[BATCH][512][NPTS];         // concat of x1..x4 (channel offsets 0,64,128,256)
__device__ int   g_pool[BATCH][1024];            // float bits, atomicMax over non-negative floats
__device__ float g_fc1[BATCH][512];
__device__ float g_fc2[BATCH][256];

// ---------------- per-point squared norm --------------------------------------
__global__ void xsq_kernel(const float* __restrict__ x, int xbs, int C) {
    int b = blockIdx.y;
    int m = blockIdx.x * blockDim.x + threadIdx.x;
    float s = 0.f;
    for (int c = 0; c < C; ++c) {
        float v = x[b * xbs + c * NPTS + m];
        s = fmaf(v, v, s);
    }
    g_xsq[b][m] = s;
}

// ---------------- kNN score matrix: score[n][m] = 2*<x_n,x_m> - xsq[m] --------
// 128x128 block tiles, 8x8 per-thread register tiles (256 threads).
// Symmetric: block (bx=n-tile, by=m-tile) runs only for by>=bx; writes the
// direct tile and (off-diagonal) the transposed tile via shared staging.
// Accumulation order (c ascending) identical to prior rounds -> bit-exact.
__global__ void dist_kernel(const float* __restrict__ x, int xbs, int C) {
    int bx = blockIdx.x, by = blockIdx.y;
    if (by < bx) return;
    __shared__ __align__(16) float As[16][132];
    __shared__ __align__(16) float Bs[16][132];
    __shared__ float sT[128][129];
    int b  = blockIdx.z;
    int n0 = bx * 128;
    int m0 = by * 128;
    int tid = threadIdx.x;
    int rn = (tid >> 4) << 3;   // n offset (0..120)
    int cm = (tid & 15) << 3;   // m offset (0..120)
    float acc[8][8];
#pragma unroll
    for (int i = 0; i < 8; i++)
#pragma unroll
        for (int j = 0; j < 8; j++) acc[i][j] = 0.f;

    for (int k0 = 0; k0 < C; k0 += 16) {
#pragma unroll 8
        for (int t = tid; t < 2048; t += 256) {
            int kk = t >> 7, nn = t & 127;
            int c = k0 + kk;
            As[kk][nn] = (c < C) ? x[b * xbs + c * NPTS + n0 + nn] : 0.f;
        }
#pragma unroll 8
        for (int t = tid; t < 2048; t += 256) {
            int kk = t >> 7, mm = t & 127;
            int c = k0 + kk;
            Bs[kk][mm] = (c < C) ? x[b * xbs + c * NPTS + m0 + mm] : 0.f;
        }
        __syncthreads();
#pragma unroll
        for (int kk = 0; kk < 16; kk++) {
            float a[8], bb[8];
            *reinterpret_cast<float4*>(a)      = *reinterpret_cast<const float4*>(&As[kk][rn]);
            *reinterpret_cast<float4*>(a + 4)  = *reinterpret_cast<const float4*>(&As[kk][rn + 4]);
            *reinterpret_cast<float4*>(bb)     = *reinterpret_cast<const float4*>(&Bs[kk][cm]);
            *reinterpret_cast<float4*>(bb + 4) = *reinterpret_cast<const float4*>(&Bs[kk][cm + 4]);
#pragma unroll
            for (int i = 0; i < 8; i++)
#pragma unroll
                for (int j = 0; j < 8; j++) acc[i][j] = fmaf(a[i], bb[j], acc[i][j]);
        }
        __syncthreads();
    }
    // direct write: score[n][m] = 2*dot - xsq[m]
    float nx[8];
#pragma unroll
    for (int j = 0; j < 8; j++) nx[j] = -g_xsq[b][m0 + cm + j];
#pragma unroll
    for (int i = 0; i < 8; i++) {
        float4 v0, v1;
        v0.x = fmaf(2.f, acc[i][0], nx[0]);
        v0.y = fmaf(2.f, acc[i][1], nx[1]);
        v0.z = fmaf(2.f, acc[i][2], nx[2]);
        v0.w = fmaf(2.f, acc[i][3], nx[3]);
        v1.x = fmaf(2.f, acc[i][4], nx[4]);
        v1.y = fmaf(2.f, acc[i][5], nx[5]);
        v1.z = fmaf(2.f, acc[i][6], nx[6]);
        v1.w = fmaf(2.f, acc[i][7], nx[7]);
        float4* dst = reinterpret_cast<float4*>(&g_dist[b][n0 + rn + i][m0 + cm]);
        dst[0] = v0; dst[1] = v1;
    }
    if (by == bx) return;   // diagonal tile covers both orders already
    // transposed write: score[m][n] = 2*dot - xsq[n] (raw dots staged)
#pragma unroll
    for (int i = 0; i < 8; i++)
#pragma unroll
        for (int j = 0; j < 8; j++)
            sT[cm + j][rn + i] = acc[i][j];
    __syncthreads();
#pragma unroll 8
    for (int t = tid; t < 16384; t += 256) {
        int mm = t >> 7, nn = t & 127;
        g_dist[b][m0 + mm][n0 + nn] = fmaf(2.f, sT[mm][nn], -g_xsq[b][n0 + nn]);
    }
}

// ---------------- top-k per row: warp-per-row register argmax extraction ------
// __launch_bounds__(256, 2): 120 regs/thread fits 2 CTAs/SM (61440 < 64K regs);
// raises occupancy 23% -> ~46% to push the 76%-busy ALU pipe toward saturation.
// Register-allocation-only change: numerics are bit-identical by construction.
__global__ void __launch_bounds__(256, 2) topk_kernel() {
    int b    = blockIdx.y;
    int warp = threadIdx.x >> 5;
    int lane = threadIdx.x & 31;
    int n    = blockIdx.x * 8 + warp;

    const float4* row = reinterpret_cast<const float4*>(&g_dist[b][n][0]);
    float val[64];
    float chmax[4];
    int   chidx[4];

#pragma unroll
    for (int q = 0; q < 16; q++) {
        float4 v = row[lane + 32 * q];
        val[q * 4 + 0] = v.x;
        val[q * 4 + 1] = v.y;
        val[q * 4 + 2] = v.z;
        val[q * 4 + 3] = v.w;
    }
    // global element index of val[j]: 4*lane + 128*(j>>2) + (j&3)
#pragma unroll
    for (int c = 0; c < 4; c++) {
        float nm = NEG_INF; int ni = 0;
#pragma unroll
        for (int i = 0; i < 16; i++) {
            int j = c * 16 + i;
            int g = 4 * lane + 128 * (j >> 2) + (j & 3);
            if (val[j] > nm) { nm = val[j]; ni = g; }
        }
        chmax[c] = nm; chidx[c] = ni;
    }

    for (int kk = 0; kk < KNN; kk++) {
        float lm = chmax[0]; int li = chidx[0];
#pragma unroll
        for (int c = 1; c < 4; c++)
            if (chmax[c] > lm) { lm = chmax[c]; li = chidx[c]; }
#pragma unroll
        for (int s = 16; s; s >>= 1) {
            float ov = __shfl_down_sync(0xffffffffu, lm, s);
            int   oi = __shfl_down_sync(0xffffffffu, li, s);
            if (ov > lm) { lm = ov; li = oi; }
        }
        lm = __shfl_sync(0xffffffffu, lm, 0);
        li = __shfl_sync(0xffffffffu, li, 0);
        if (lane == 0) g_idx[b][n][kk] = li;
        if (((li >> 2) & 31) == lane) {
            bool done = false;
#pragma unroll
            for (int c = 0; c < 4; c++) {
                if (!done && chmax[c] == lm) {
                    done = true;
                    float nm = NEG_INF; int ni = 0;
#pragma unroll
                    for (int i = 0; i < 16; i++) {
                        int j = c * 16 + i;
                        if (val[j] == lm) val[j] = NEG_INF;
                        int g = 4 * lane + 128 * (j >> 2) + (j & 3);
                        if (val[j] > nm) { nm = val[j]; ni = g; }
                    }
                    chmax[c] = nm; chidx[c] = ni;
                }
            }
        }
    }
}

// ---------------- y/t GEMM: out[b][m][o] for o in [0,2Co): y then t ----------
// 128(o) x 128(m) block tiles, 8x8 per-thread.
// row(o,c): o<Co -> w[o][c] (= Wa), else w[o-Co][C+c] - w[o-Co][c] (= Wb-Wa)
__global__ void yt_kernel(const float* __restrict__ x, int xbs, int C,
                          const float* __restrict__ w, int Co) {
    __shared__ __align__(16) float Ws[16][132];
    __shared__ __align__(16) float Xs[16][132];
    int b  = blockIdx.z;
    int o0 = blockIdx.x * 128;
    int m0 = blockIdx.y * 128;
    int tid = threadIdx.x;
    int ro = (tid >> 4) << 3;
    int cm = (tid & 15) << 3;
    int twoC = 2 * C;
    float acc[8][8];
#pragma unroll
    for (int i = 0; i < 8; i++)
#pragma unroll
        for (int j = 0; j < 8; j++) acc[i][j] = 0.f;

    for (int k0 = 0; k0 < C; k0 += 16) {
#pragma unroll 8
        for (int t = tid; t < 2048; t += 256) {
            int kk = t & 15, oo = t >> 4;
            int c = k0 + kk;
            float wv = 0.f;
            if (c < C) {
                int o = o0 + oo;
                if (o < Co) wv = w[o * twoC + c];
                else {
                    int o2 = o - Co;
                    wv = w[o2 * twoC + C + c] - w[o2 * twoC + c];
                }
            }
            Ws[kk][oo] = wv;
        }
#pragma unroll 8
        for (int t = tid; t < 2048; t += 256) {
            int kk = t >> 7, mm = t & 127;
            int c = k0 + kk;
            Xs[kk][mm] = (c < C) ? x[b * xbs + c * NPTS + m0 + mm] : 0.f;
        }
        __syncthreads();
#pragma unroll
        for (int kk = 0; kk < 16; kk++) {
            float a[8], bb[8];
            *reinterpret_cast<float4*>(a)      = *reinterpret_cast<const float4*>(&Ws[kk][ro]);
            *reinterpret_cast<float4*>(a + 4)  = *reinterpret_cast<const float4*>(&Ws[kk][ro + 4]);
            *reinterpret_cast<float4*>(bb)     = *reinterpret_cast<const float4*>(&Xs[kk][cm]);
            *reinterpret_cast<float4*>(bb + 4) = *reinterpret_cast<const float4*>(&Xs[kk][cm + 4]);
#pragma unroll
            for (int i = 0; i < 8; i++)
#pragma unroll
                for (int j = 0; j < 8; j++) acc[i][j] = fmaf(a[i], bb[j], acc[i][j]);
        }
        __syncthreads();
    }
#pragma unroll
    for (int j = 0; j < 8; j++) {
        float4 v0 = make_float4(acc[0][j], acc[1][j], acc[2][j], acc[3][j]);
        float4 v1 = make_float4(acc[4][j], acc[5][j], acc[6][j], acc[7][j]);
        *reinterpret_cast<float4*>(&g_yt[b][m0 + cm + j][o0 + ro])     = v0;
        *reinterpret_cast<float4*>(&g_yt[b][m0 + cm + j][o0 + ro + 4]) = v1;
    }
}

// ---------------- gather + max_k + bn/relu, transposed write into concat buf --
__global__ void gathermax_kernel(int Co, const float* __restrict__ bg,
                                 const float* __restrict__ bb, int chanoff) {
    __shared__ int   sidx[32][KNN];
    __shared__ float sval[32][257];   // padded: stride 257 -> conflict-free transpose
    int b  = blockIdx.y;
    int n0 = blockIdx.x * 32;
    int tid = threadIdx.x;
    for (int t = tid; t < 32 * KNN; t += 256)
        sidx[t / KNN][t % KNN] = g_idx[b][n0 + t / KNN][t % KNN];
    __syncthreads();
    for (int t = tid; t < 32 * Co; t += 256) {
        int nn = t / Co, o = t - nn * Co;
        float mv = NEG_INF;
#pragma unroll
        for (int kk = 0; kk < KNN; kk++)
            mv = fmaxf(mv, g_yt[b][sidx[nn][kk]][o]);
        float tv = g_yt[b][n0 + nn][Co + o];
        float s  = bg[o] * BN_INV;
        sval[nn][o] = fmaxf(fmaf(s, mv + tv, bb[o]), 0.f);
    }
    __syncthreads();
    for (int t = tid; t < 32 * Co; t += 256) {
        int o = t >> 5, nn = t & 31;
        g_xc[b][chanoff + o][n0 + nn] = sval[nn][o];
    }
}

// ---------------- conv5 (1024x512 GEMM) + bn/relu + global max over n ---------
__global__ void init_pool_kernel() { g_pool[blockIdx.x][threadIdx.x] = 0; }

__global__ void conv5_kernel(const float* __restrict__ w5,
                             const float* __restrict__ g5,
                             const float* __restrict__ b5) {
    __shared__ __align__(16) float Ws[16][132];
    __shared__ __align__(16) float Xs[16][132];
    __shared__ float sred[128][17];
    int b  = blockIdx.z;
    int o0 = blockIdx.x * 128;
    int n0 = blockIdx.y * 128;
    int tid = threadIdx.x;
    int ro = (tid >> 4) << 3;
    int cn = (tid & 15) << 3;
    float acc[8][8];
#pragma unroll
    for (int i = 0; i < 8; i++)
#pragma unroll
        for (int j = 0; j < 8; j++) acc[i][j] = 0.f;

    for (int k0 = 0; k0 < 512; k0 += 16) {
#pragma unroll 8
        for (int t = tid; t < 2048; t += 256) {
            int kk = t & 15, oo = t >> 4;
            Ws[kk][oo] = w5[(o0 + oo) * 512 + k0 + kk];
        }
#pragma unroll 8
        for (int t = tid; t < 2048; t += 256) {
            int kk = t >> 7, nn = t & 127;
            Xs[kk][nn] = g_xc[b][k0 + kk][n0 + nn];
        }
        __syncthreads();
#pragma unroll
        for (int kk = 0; kk < 16; kk++) {
            float a[8], bb[8];
            *reinterpret_cast<float4*>(a)      = *reinterpret_cast<const float4*>(&Ws[kk][ro]);
            *reinterpret_cast<float4*>(a + 4)  = *reinterpret_cast<const float4*>(&Ws[kk][ro + 4]);
            *reinterpret_cast<float4*>(bb)     = *reinterpret_cast<const float4*>(&Xs[kk][cn]);
            *reinterpret_cast<float4*>(bb + 4) = *reinterpret_cast<const float4*>(&Xs[kk][cn + 4]);
#pragma unroll
            for (int i = 0; i < 8; i++)
#pragma unroll
                for (int j = 0; j < 8; j++) acc[i][j] = fmaf(a[i], bb[j], acc[i][j]);
        }
        __syncthreads();
    }
#pragma unroll
    for (int i = 0; i < 8; i++) {
        float s = g5[o0 + ro + i] * BN_INV;
        float bias = b5[o0 + ro + i];
        float m = 0.f;
#pragma unroll
        for (int j = 0; j < 8; j++)
            m = fmaxf(m, fmaxf(fmaf(s, acc[i][j], bias), 0.f));
        sred[ro + i][tid & 15] = m;
    }
    __syncthreads();
    if (tid < 128) {
        float m = sred[tid][0];
#pragma unroll
        for (int c = 1; c < 16; c++) m = fmaxf(m, sred[tid][c]);
        atomicMax(&g_pool[b][o0 + tid], __float_as_int(m));  // m >= 0: int bits ordered
    }
}

// ---------------- FC head -----------------------------------------------------
__device__ __forceinline__ float warp_sum(float v) {
#pragma unroll
    for (int s = 16; s > 0; s >>= 1) v += __shfl_down_sync(0xffffffffu, v, s);
    return v;
}

__global__ void fc1_kernel(const float* __restrict__ w, const float* __restrict__ bg,
                           const float* __restrict__ bb) {
    int gw   = (blockIdx.x * blockDim.x + threadIdx.x) >> 5;
    int lane = threadIdx.x & 31;
    if (gw >= BATCH * 512) return;
    int b = gw >> 9, j = gw & 511;
    const float* in = reinterpret_cast<const float*>(&g_pool[b][0]);
    float acc = 0.f;
    for (int i = lane; i < 1024; i += 32) acc = fmaf(in[i], w[j * 1024 + i], acc);
    acc = warp_sum(acc);
    if (lane == 0) g_fc1[b][j] = fmaxf(fmaf(bg[j] * BN_INV, acc, bb[j]), 0.f);
}

__global__ void fc2_kernel(const float* __restrict__ w, const float* __restrict__ bg,
                           const float* __restrict__ bb) {
    int gw   = (blockIdx.x * blockDim.x + threadIdx.x) >> 5;
    int lane = threadIdx.x & 31;
    if (gw >= BATCH * 256) return;
    int b = gw >> 8, j = gw & 255;
    float acc = 0.f;
    for (int i = lane; i < 512; i += 32) acc = fmaf(g_fc1[b][i], w[j * 512 + i], acc);
    acc = warp_sum(acc);
    if (lane == 0) g_fc2[b][j] = fmaxf(fmaf(bg[j] * BN_INV, acc, bb[j]), 0.f);
}

__global__ void fc3_kernel(const float* __restrict__ w, float* __restrict__ out) {
    int gw   = (blockIdx.x * blockDim.x + threadIdx.x) >> 5;
    int lane = threadIdx.x & 31;
    if (gw >= BATCH * 40) return;
    int b = gw / 40, j = gw % 40;
    float acc = 0.f;
    for (int i = lane; i < 256; i += 32) acc = fmaf(g_fc2[b][i], w[j * 256 + i], acc);
    acc = warp_sum(acc);
    if (lane == 0) out[b * 40 + j] = acc;
}

// ---------------- host driver --------------------------------------------------
static void run_layer(const float* x, int xbs, int C, const float* w, int Co,
                      const float* bg, const float* bb, int chanoff) {
    xsq_kernel<<<dim3(NPTS / 256, BATCH), 256>>>(x, xbs, C);
    yt_kernel<<<dim3(2 * Co / 128, NPTS / 128, BATCH), 256>>>(x, xbs, C, w, Co);
    dist_kernel<<<dim3(16, 16, BATCH), 256>>>(x, xbs, C);
    topk_kernel<<<dim3(NPTS / 8, BATCH), 256>>>();
    gathermax_kernel<<<dim3(NPTS / 32, BATCH), 256>>>(Co, bg, bb, chanoff);
}

extern "C" void kernel_launch(void* const* d_in, const int* in_sizes, int n_in,
                              void* d_out, int out_size) {
    const float* x   = (const float*)d_in[0];
    const float* w1  = (const float*)d_in[1];
    const float* w2  = (const float*)d_in[2];
    const float* w3  = (const float*)d_in[3];
    const float* w4  = (const float*)d_in[4];
    const float* w5  = (const float*)d_in[5];
    const float* fw1 = (const float*)d_in[6];
    const float* fw2 = (const float*)d_in[7];
    const float* fw3 = (const float*)d_in[8];
    const float* g1 = (const float*)d_in[9],  *b1 = (const float*)d_in[10];
    const float* g2 = (const float*)d_in[11], *b2 = (const float*)d_in[12];
    const float* g3 = (const float*)d_in[13], *b3 = (const float*)d_in[14];
    const float* g4 = (const float*)d_in[15], *b4 = (const float*)d_in[16];
    const float* g5 = (const float*)d_in[17], *b5 = (const float*)d_in[18];
    const float* g6 = (const float*)d_in[19], *b6 = (const float*)d_in[20];
    const float* g7 = (const float*)d_in[21], *b7 = (const float*)d_in[22];

    float* xc = nullptr;
    cudaGetSymbolAddress((void**)&xc, g_xc);

    init_pool_kernel<<<BATCH, 1024>>>();

    run_layer(x,                3 * NPTS,   3,   w1, 64,  g1, b1, 0);
    run_layer(xc,               512 * NPTS, 64,  w2, 64,  g2, b2, 64);
    run_layer(xc + 64 * NPTS,   512 * NPTS, 64,  w3, 128, g3, b3, 128);
    run_layer(xc + 128 * NPTS,  512 * NPTS, 128, w4, 256, g4, b4, 256);

    conv5_kernel<<<dim3(8, 16, BATCH), 256>>>(w5, g5, b5);

    fc1_kernel<<<512, 256>>>(fw1, g6, b6);
    fc2_kernel<<<256, 256>>>(fw2, g7, b7);
    fc3_kernel<<<40, 256>>>(fw3, (float*)d_out);
}